// round 1
// baseline (speedup 1.0000x reference)
#include <cuda_runtime.h>
#include <math.h>

// Problem constants (from reference): N=50000, P=1.6M, F=128, G=16, H=32,
// HID1=256, HID2=128, IN_F=320, out cols = 130.
#define NMAX 50000

// Scratch (device globals: allocation-free rule)
__device__ float g_acc[NMAX * 64];            // [n][0:16]=Gsum, [16:64]=GVsum(d,g)
__device__ float g_M[(size_t)NMAX * 512];     // M[n][g*32+h] = emb @ agh
__device__ float g_msg[(size_t)NMAX * 320];   // MLP input

__device__ __forceinline__ float gelu_exact(float x) {
    return 0.5f * x * (1.0f + erff(x * 0.70710678118654752f));
}

// ---------------------------------------------------------------------------
// K1: zero the pair accumulators (graph replays need fresh zeros every call)
// ---------------------------------------------------------------------------
__global__ void k_zero_acc(int N) {
    int i = blockIdx.x * blockDim.x + threadIdx.x;
    if (i < N * 16) reinterpret_cast<float4*>(g_acc)[i] = make_float4(0.f, 0.f, 0.f, 0.f);
}

// ---------------------------------------------------------------------------
// K2: scatter gs (16f) + gv (48f) per pair into g_acc via vector RED.
// quad index q = p*16 + c ; c<4 -> gs chunk, c>=4 -> gv chunk
// ---------------------------------------------------------------------------
__global__ void k_scatter(const int* __restrict__ idxj, const float* __restrict__ gs,
                          const float* __restrict__ gv, int P) {
    long long q = (long long)blockIdx.x * blockDim.x + threadIdx.x;
    long long total = (long long)P * 16;
    if (q >= total) return;
    int p = (int)(q >> 4);
    int c = (int)(q & 15);
    int n = idxj[p];
    float4 v;
    float* dst;
    if (c < 4) {
        v = *reinterpret_cast<const float4*>(gs + (size_t)p * 16 + c * 4);
        dst = g_acc + (size_t)n * 64 + c * 4;
    } else {
        v = *reinterpret_cast<const float4*>(gv + (size_t)p * 48 + (c - 4) * 4);
        dst = g_acc + (size_t)n * 64 + 16 + (c - 4) * 4;
    }
    asm volatile("red.global.add.v4.f32 [%0], {%1,%2,%3,%4};"
                 :: "l"(dst), "f"(v.x), "f"(v.y), "f"(v.z), "f"(v.w)
                 : "memory");
}

// ---------------------------------------------------------------------------
// K3: M (N,512) = emb (N,128) @ agh reshaped (128,512).
// CTA tile: 64 atoms x 256 cols, K=128 fully staged in smem. 256 threads,
// each computes an 8x8 register tile.
// ---------------------------------------------------------------------------
__global__ void __launch_bounds__(256) k_gemm_M(const float* __restrict__ emb,
                                                const float* __restrict__ agh, int N) {
    extern __shared__ float sm[];
    float* emb_s = sm;              // 64*128
    float* agh_s = sm + 64 * 128;   // 128*256
    int a0 = blockIdx.x * 64;
    int cb = blockIdx.y;            // column block: 0 or 1
    int tid = threadIdx.x;

    for (int i = tid; i < 64 * 128; i += 256) {
        int r = i >> 7, f = i & 127;
        int n = a0 + r;
        emb_s[i] = (n < N) ? emb[(size_t)n * 128 + f] : 0.f;
    }
    for (int i = tid; i < 128 * 256; i += 256) {
        int k = i >> 8, j = i & 255;
        agh_s[i] = agh[(size_t)k * 512 + cb * 256 + j];
    }
    __syncthreads();

    int tx = tid & 31, ty = tid >> 5;
    float acc[8][8];
    #pragma unroll
    for (int i = 0; i < 8; i++)
        #pragma unroll
        for (int c = 0; c < 8; c++) acc[i][c] = 0.f;

    for (int k = 0; k < 128; k++) {
        float w[8], x[8];
        #pragma unroll
        for (int c = 0; c < 8; c++) w[c] = agh_s[k * 256 + tx + 32 * c];
        #pragma unroll
        for (int i = 0; i < 8; i++) x[i] = emb_s[(ty * 8 + i) * 128 + k];
        #pragma unroll
        for (int i = 0; i < 8; i++)
            #pragma unroll
            for (int c = 0; c < 8; c++) acc[i][c] += x[i] * w[c];
    }

    #pragma unroll
    for (int i = 0; i < 8; i++) {
        int n = a0 + ty * 8 + i;
        if (n < N) {
            #pragma unroll
            for (int c = 0; c < 8; c++)
                g_M[(size_t)n * 512 + cb * 256 + tx + 32 * c] = acc[i][c];
        }
    }
}

// ---------------------------------------------------------------------------
// K4: per-atom assemble of msg (320):
//   mapped[f] = Gsum . W_gf[:,f] ; rad_emb = emb*mapped ; rad_q = q*mapped
//   avf[h,d]  = sum_g GVsum[d,g] * M[n,g*32+h] ; vec_emb[h] = safe_norm
// One CTA (128 threads) per atom; thread t == feature f.
// ---------------------------------------------------------------------------
__global__ void k_assemble(const float* __restrict__ emb, const float* __restrict__ q,
                           const float* __restrict__ Wgf, int N) {
    int n = blockIdx.x;
    if (n >= N) return;
    __shared__ float s[64];
    int t = threadIdx.x;
    if (t < 64) s[t] = g_acc[(size_t)n * 64 + t];
    __syncthreads();

    float m = 0.f;
    #pragma unroll
    for (int g = 0; g < 16; g++) m += s[g] * Wgf[g * 128 + t];

    float e = emb[(size_t)n * 128 + t];
    float qq = q[n];
    float* msg = g_msg + (size_t)n * 320;
    msg[t] = e * m;           // rad_emb
    msg[160 + t] = qq * m;    // rad_q

    if (t < 32) {
        int h = t;
        float a0 = 0.f, a1 = 0.f, a2 = 0.f;
        const float* Mrow = g_M + (size_t)n * 512;
        #pragma unroll
        for (int g = 0; g < 16; g++) {
            float Mv = Mrow[g * 32 + h];
            a0 += s[16 + 0 * 16 + g] * Mv;
            a1 += s[16 + 1 * 16 + g] * Mv;
            a2 += s[16 + 2 * 16 + g] * Mv;
        }
        float sq = a0 * a0 + a1 * a1 + a2 * a2;
        msg[128 + h] = (sq > 0.f) ? sqrtf(sq) : 0.f;  // vec_emb (safe_norm)
        msg[288 + h] = 0.f;                           // vec_q zeros
    }
}

// ---------------------------------------------------------------------------
// K5: fused 3-layer MLP. CTA tile = 64 atoms, 256 threads. Activations live
// in smem across layers; weights stream from L1/L2 (broadcast across CTAs).
// Writes final outputs directly into d_out in (delta_a | delta_q | f) layout.
// ---------------------------------------------------------------------------
__global__ void __launch_bounds__(256) k_mlp(
    const float* __restrict__ W1, const float* __restrict__ b1,
    const float* __restrict__ W2, const float* __restrict__ b2,
    const float* __restrict__ W3, const float* __restrict__ b3,
    float* __restrict__ out, int N) {
    extern __shared__ float sm[];
    float* msg_s = sm;                       // 64*320
    float* h1_s  = sm + 64 * 320;            // 64*256
    float* h2_s  = h1_s + 64 * 256;          // 64*128
    int a0 = blockIdx.x * 64;
    int tid = threadIdx.x, tx = tid & 31, ty = tid >> 5;

    for (int i = tid; i < 64 * 320; i += 256) {
        int r = i / 320, k = i - r * 320;
        int n = a0 + r;
        msg_s[i] = (n < N) ? g_msg[(size_t)n * 320 + k] : 0.f;
    }
    __syncthreads();

    // ---- Layer 1: 320 -> 256, gelu ----
    {
        float acc[8][8];
        #pragma unroll
        for (int i = 0; i < 8; i++)
            #pragma unroll
            for (int c = 0; c < 8; c++) acc[i][c] = 0.f;
        for (int k = 0; k < 320; k++) {
            float w[8];
            #pragma unroll
            for (int c = 0; c < 8; c++) w[c] = W1[(size_t)k * 256 + tx + 32 * c];
            #pragma unroll
            for (int i = 0; i < 8; i++) {
                float x = msg_s[(ty * 8 + i) * 320 + k];
                #pragma unroll
                for (int c = 0; c < 8; c++) acc[i][c] += x * w[c];
            }
        }
        #pragma unroll
        for (int i = 0; i < 8; i++)
            #pragma unroll
            for (int c = 0; c < 8; c++) {
                int j = tx + 32 * c;
                h1_s[(ty * 8 + i) * 256 + j] = gelu_exact(acc[i][c] + b1[j]);
            }
    }
    __syncthreads();

    // ---- Layer 2: 256 -> 128, gelu ----
    {
        float acc[8][4];
        #pragma unroll
        for (int i = 0; i < 8; i++)
            #pragma unroll
            for (int c = 0; c < 4; c++) acc[i][c] = 0.f;
        for (int k = 0; k < 256; k++) {
            float w[4];
            #pragma unroll
            for (int c = 0; c < 4; c++) w[c] = W2[(size_t)k * 128 + tx + 32 * c];
            #pragma unroll
            for (int i = 0; i < 8; i++) {
                float x = h1_s[(ty * 8 + i) * 256 + k];
                #pragma unroll
                for (int c = 0; c < 4; c++) acc[i][c] += x * w[c];
            }
        }
        #pragma unroll
        for (int i = 0; i < 8; i++)
            #pragma unroll
            for (int c = 0; c < 4; c++) {
                int j = tx + 32 * c;
                h2_s[(ty * 8 + i) * 128 + j] = gelu_exact(acc[i][c] + b2[j]);
            }
    }
    __syncthreads();

    // ---- Layer 3: 128 -> 130, linear, scatter to output layout ----
    {
        float acc[8][5];
        #pragma unroll
        for (int i = 0; i < 8; i++)
            #pragma unroll
            for (int c = 0; c < 5; c++) acc[i][c] = 0.f;
        for (int k = 0; k < 128; k++) {
            float w[5];
            #pragma unroll
            for (int c = 0; c < 5; c++) {
                int j = tx + 32 * c;
                w[c] = (j < 130) ? W3[(size_t)k * 130 + j] : 0.f;
            }
            #pragma unroll
            for (int i = 0; i < 8; i++) {
                float x = h2_s[(ty * 8 + i) * 128 + k];
                #pragma unroll
                for (int c = 0; c < 5; c++) acc[i][c] += x * w[c];
            }
        }
        size_t dq_off = (size_t)N * 128;
        size_t f_off  = dq_off + (size_t)N;
        #pragma unroll
        for (int i = 0; i < 8; i++) {
            int n = a0 + ty * 8 + i;
            if (n >= N) continue;
            #pragma unroll
            for (int c = 0; c < 5; c++) {
                int j = tx + 32 * c;
                if (j >= 130) continue;
                float v = acc[i][c] + b3[j];
                if (j == 0)      out[dq_off + n] = v;           // delta_q
                else if (j == 1) out[f_off + n]  = v;           // f
                else             out[(size_t)n * 128 + (j - 2)] = v;  // delta_a
            }
        }
    }
}

// ---------------------------------------------------------------------------
extern "C" void kernel_launch(void* const* d_in, const int* in_sizes, int n_in,
                              void* d_out, int out_size) {
    const float* emb  = (const float*)d_in[0];
    const float* q    = (const float*)d_in[1];
    const int*   pidx = (const int*)d_in[2];
    const float* gs   = (const float*)d_in[3];
    const float* gv   = (const float*)d_in[4];
    const float* agh  = (const float*)d_in[5];
    const float* Wgf  = (const float*)d_in[6];
    const float* W1   = (const float*)d_in[7];
    const float* b1   = (const float*)d_in[8];
    const float* W2   = (const float*)d_in[9];
    const float* b2   = (const float*)d_in[10];
    const float* W3   = (const float*)d_in[11];
    const float* b3   = (const float*)d_in[12];
    float* out = (float*)d_out;

    int N = in_sizes[0] / 128;
    int P = in_sizes[2] / 2;
    if (N > NMAX) N = NMAX;
    const int* idxj = pidx + P;   // pair_indices row 1

    // K1: zero accumulators
    int zb = (N * 16 + 255) / 256;
    k_zero_acc<<<zb, 256>>>(N);

    // K2: pair scatter (vector RED)
    long long Q = (long long)P * 16;
    int sb = (int)((Q + 255) / 256);
    k_scatter<<<sb, 256>>>(idxj, gs, gv, P);

    // K3: M = emb @ agh
    cudaFuncSetAttribute(k_gemm_M, cudaFuncAttributeMaxDynamicSharedMemorySize, 163840);
    dim3 g3((N + 63) / 64, 2);
    k_gemm_M<<<g3, 256, 163840>>>(emb, agh, N);

    // K4: assemble msg
    k_assemble<<<N, 128>>>(emb, q, Wgf, N);

    // K5: fused MLP -> d_out
    cudaFuncSetAttribute(k_mlp, cudaFuncAttributeMaxDynamicSharedMemorySize, 180224);
    k_mlp<<<(N + 63) / 64, 256, 180224>>>(W1, b1, W2, b2, W3, b3, out, N);
}

// round 2
// speedup vs baseline: 2.1857x; 2.1857x over previous
#include <cuda_runtime.h>
#include <math.h>
#include <stdint.h>

// N=50000, P=1.6M, F=128, G=16, H=32, HID1=256, HID2=128, IN=288 (vec_q==0 dropped)
#define NMAX 50000

__device__ float g_acc[NMAX * 64];            // [n][0:16]=Gsum, [16:64]=GVsum(d,g)
__device__ float g_M[(size_t)NMAX * 512];     // M[n][g*32+h] = emb @ agh
__device__ float g_msg[(size_t)NMAX * 288];   // MLP input (288 cols)

__device__ __forceinline__ float gelu_exact(float x) {
    return 0.5f * x * (1.0f + erff(x * 0.70710678118654752f));
}
__device__ __forceinline__ float f2tf(float x) {
    uint32_t r;
    asm("cvt.rna.tf32.f32 %0, %1;" : "=r"(r) : "f"(x));
    return __uint_as_float(r);
}
__device__ __forceinline__ void mma_tf32(float d[4], const uint32_t a[4],
                                         const uint32_t b[2]) {
    asm volatile(
        "mma.sync.aligned.m16n8k8.row.col.f32.tf32.tf32.f32 "
        "{%0,%1,%2,%3}, {%4,%5,%6,%7}, {%8,%9}, {%0,%1,%2,%3};"
        : "+f"(d[0]), "+f"(d[1]), "+f"(d[2]), "+f"(d[3])
        : "r"(a[0]), "r"(a[1]), "r"(a[2]), "r"(a[3]), "r"(b[0]), "r"(b[1]));
}
__device__ __forceinline__ uint32_t fu(float x) { return __float_as_uint(x); }

// ---------------------------------------------------------------------------
// K1: zero pair accumulators
// ---------------------------------------------------------------------------
__global__ void k_zero_acc(int N) {
    int i = blockIdx.x * blockDim.x + threadIdx.x;
    if (i < N * 16) reinterpret_cast<float4*>(g_acc)[i] = make_float4(0.f, 0.f, 0.f, 0.f);
}

// ---------------------------------------------------------------------------
// K2: scatter gs(16) + gv(48) per pair via red.global.add.v4.f32
// ---------------------------------------------------------------------------
__global__ void k_scatter(const int* __restrict__ idxj, const float* __restrict__ gs,
                          const float* __restrict__ gv, int P) {
    long long q = (long long)blockIdx.x * blockDim.x + threadIdx.x;
    long long total = (long long)P * 16;
    if (q >= total) return;
    int p = (int)(q >> 4);
    int c = (int)(q & 15);
    int n = idxj[p];
    float4 v;
    float* dst;
    if (c < 4) {
        v = *reinterpret_cast<const float4*>(gs + (size_t)p * 16 + c * 4);
        dst = g_acc + (size_t)n * 64 + c * 4;
    } else {
        v = *reinterpret_cast<const float4*>(gv + (size_t)p * 48 + (c - 4) * 4);
        dst = g_acc + (size_t)n * 64 + 16 + (c - 4) * 4;
    }
    asm volatile("red.global.add.v4.f32 [%0], {%1,%2,%3,%4};"
                 :: "l"(dst), "f"(v.x), "f"(v.y), "f"(v.z), "f"(v.w)
                 : "memory");
}

// ---------------------------------------------------------------------------
// K3: M (N,512) = emb (N,128) @ agh (128,512) — tf32 mma.sync
// CTA: 64 atoms x 256 cols (grid.y=2 halves), 256 threads = 8 warps (2m x 4n)
// ---------------------------------------------------------------------------
#define XS3 132   // 128 + 4 pad (A-frag conflict-free)
#define WS3 264   // 256 + 8 pad (B-frag conflict-free)
__global__ void __launch_bounds__(256) k_gemm_M_tc(const float* __restrict__ emb,
                                                   const float* __restrict__ agh, int N) {
    extern __shared__ float sm[];
    float* Xs = sm;                 // 64 x 132
    float* Ws = sm + 64 * XS3;      // 128 x 264
    int a0 = blockIdx.x * 64;
    int cb = blockIdx.y;
    int tid = threadIdx.x;

    for (int i = tid; i < 64 * 128; i += 256) {
        int r = i >> 7, f = i & 127;
        int n = a0 + r;
        Xs[r * XS3 + f] = f2tf((n < N) ? emb[(size_t)n * 128 + f] : 0.f);
    }
    for (int i = tid; i < 128 * 256; i += 256) {
        int k = i >> 8, j = i & 255;
        Ws[k * WS3 + j] = f2tf(agh[(size_t)k * 512 + cb * 256 + j]);
    }
    __syncthreads();

    int lane = tid & 31, warp = tid >> 5;
    int gid = lane >> 2, tig = lane & 3;
    int wm = warp >> 2, wn = warp & 3;   // 2 x 4

    float acc[2][8][4];
    #pragma unroll
    for (int mt = 0; mt < 2; mt++)
        #pragma unroll
        for (int nt = 0; nt < 8; nt++)
            #pragma unroll
            for (int e = 0; e < 4; e++) acc[mt][nt][e] = 0.f;

    #pragma unroll
    for (int k = 0; k < 128; k += 8) {
        uint32_t A[2][4];
        #pragma unroll
        for (int mt = 0; mt < 2; mt++) {
            int row = 32 * wm + 16 * mt + gid;
            A[mt][0] = fu(Xs[row * XS3 + k + tig]);
            A[mt][1] = fu(Xs[(row + 8) * XS3 + k + tig]);
            A[mt][2] = fu(Xs[row * XS3 + k + tig + 4]);
            A[mt][3] = fu(Xs[(row + 8) * XS3 + k + tig + 4]);
        }
        uint32_t B[8][2];
        #pragma unroll
        for (int nt = 0; nt < 8; nt++) {
            int col = 64 * wn + 8 * nt + gid;
            B[nt][0] = fu(Ws[(k + tig) * WS3 + col]);
            B[nt][1] = fu(Ws[(k + tig + 4) * WS3 + col]);
        }
        #pragma unroll
        for (int mt = 0; mt < 2; mt++)
            #pragma unroll
            for (int nt = 0; nt < 8; nt++) mma_tf32(acc[mt][nt], A[mt], B[nt]);
    }

    #pragma unroll
    for (int mt = 0; mt < 2; mt++) {
        int r0 = 32 * wm + 16 * mt + gid;
        #pragma unroll
        for (int nt = 0; nt < 8; nt++) {
            int col = cb * 256 + 64 * wn + 8 * nt + 2 * tig;
            int n1 = a0 + r0, n2 = a0 + r0 + 8;
            if (n1 < N) {
                g_M[(size_t)n1 * 512 + col] = acc[mt][nt][0];
                g_M[(size_t)n1 * 512 + col + 1] = acc[mt][nt][1];
            }
            if (n2 < N) {
                g_M[(size_t)n2 * 512 + col] = acc[mt][nt][2];
                g_M[(size_t)n2 * 512 + col + 1] = acc[mt][nt][3];
            }
        }
    }
}

// ---------------------------------------------------------------------------
// K4: per-atom assemble of msg (288): rad_emb | vec_emb | rad_q
// ---------------------------------------------------------------------------
__global__ void k_assemble(const float* __restrict__ emb, const float* __restrict__ q,
                           const float* __restrict__ Wgf, int N) {
    int n = blockIdx.x;
    if (n >= N) return;
    __shared__ float s[64];
    int t = threadIdx.x;
    if (t < 64) s[t] = g_acc[(size_t)n * 64 + t];
    __syncthreads();

    float m = 0.f;
    #pragma unroll
    for (int g = 0; g < 16; g++) m += s[g] * Wgf[g * 128 + t];

    float e = emb[(size_t)n * 128 + t];
    float qq = q[n];
    float* msg = g_msg + (size_t)n * 288;
    msg[t] = e * m;
    msg[160 + t] = qq * m;

    if (t < 32) {
        int h = t;
        float a0 = 0.f, a1 = 0.f, a2 = 0.f;
        const float* Mrow = g_M + (size_t)n * 512;
        #pragma unroll
        for (int g = 0; g < 16; g++) {
            float Mv = Mrow[g * 32 + h];
            a0 += s[16 + g] * Mv;
            a1 += s[32 + g] * Mv;
            a2 += s[48 + g] * Mv;
        }
        float sq = a0 * a0 + a1 * a1 + a2 * a2;
        msg[128 + h] = (sq > 0.f) ? sqrtf(sq) : 0.f;
    }
}

// ---------------------------------------------------------------------------
// K5: fused 3-layer MLP, tf32 mma.sync. CTA = 64 atoms, 256 threads (8 warps).
// smem regions: R0 = Xs(64x292) / reused as H1(64x260)
//               R1 = weight staging buffer (max 96x264)
//               R2 = H2(64x132)
// ---------------------------------------------------------------------------
#define XSP 292   // 288 + 4
#define H1P 260   // 256 + 4
#define H2P 132   // 128 + 4
#define W1P 264   // 256 + 8
#define W2P 136   // 128 + 8
#define W3P 136   // 136 (130 padded), +8 rule: 136%32==8 ok
#define R0_OFF 0
#define R1_OFF (64 * XSP)                 // 18688
#define R2_OFF (R1_OFF + 96 * W1P)        // 18688 + 25344 = 44032
#define MLP_SMEM ((R2_OFF + 64 * H2P) * 4)  // (44032+8448)*4 = 209920 B

__global__ void __launch_bounds__(256) k_mlp_tc(
    const float* __restrict__ W1, const float* __restrict__ b1,
    const float* __restrict__ W2, const float* __restrict__ b2,
    const float* __restrict__ W3, const float* __restrict__ b3,
    float* __restrict__ out, int N) {
    extern __shared__ float sm[];
    float* Xs = sm + R0_OFF;
    float* H1 = sm + R0_OFF;
    float* Wb = sm + R1_OFF;
    float* H2 = sm + R2_OFF;
    int a0 = blockIdx.x * 64;
    int tid = threadIdx.x;
    int lane = tid & 31, warp = tid >> 5;
    int gid = lane >> 2, tig = lane & 3;
    int wm = warp >> 2, wn = warp & 3;   // 2 x 4

    // stage msg (tf32)
    for (int i = tid; i < 64 * 288; i += 256) {
        int r = i / 288, k = i - r * 288;
        int n = a0 + r;
        Xs[r * XSP + k] = f2tf((n < N) ? g_msg[(size_t)n * 288 + k] : 0.f);
    }

    // ================= Layer 1: 288 -> 256, gelu =================
    float acc1[2][8][4];
    #pragma unroll
    for (int mt = 0; mt < 2; mt++)
        #pragma unroll
        for (int nt = 0; nt < 8; nt++)
            #pragma unroll
            for (int e = 0; e < 4; e++) acc1[mt][nt][e] = 0.f;

    for (int kc = 0; kc < 3; kc++) {
        __syncthreads();
        // stage W1 chunk [kc*96, kc*96+96) x 256
        for (int i = tid; i < 96 * 256; i += 256) {
            int r = i >> 8, c = i & 255;
            Wb[r * W1P + c] = f2tf(W1[(size_t)(kc * 96 + r) * 256 + c]);
        }
        __syncthreads();
        #pragma unroll
        for (int ks = 0; ks < 96; ks += 8) {
            int kg = kc * 96 + ks;
            uint32_t A[2][4];
            #pragma unroll
            for (int mt = 0; mt < 2; mt++) {
                int row = 32 * wm + 16 * mt + gid;
                A[mt][0] = fu(Xs[row * XSP + kg + tig]);
                A[mt][1] = fu(Xs[(row + 8) * XSP + kg + tig]);
                A[mt][2] = fu(Xs[row * XSP + kg + tig + 4]);
                A[mt][3] = fu(Xs[(row + 8) * XSP + kg + tig + 4]);
            }
            uint32_t B[8][2];
            #pragma unroll
            for (int nt = 0; nt < 8; nt++) {
                int col = 64 * wn + 8 * nt + gid;
                B[nt][0] = fu(Wb[(ks + tig) * W1P + col]);
                B[nt][1] = fu(Wb[(ks + tig + 4) * W1P + col]);
            }
            #pragma unroll
            for (int mt = 0; mt < 2; mt++)
                #pragma unroll
                for (int nt = 0; nt < 8; nt++) mma_tf32(acc1[mt][nt], A[mt], B[nt]);
        }
    }
    __syncthreads();   // all A-reads of Xs done; safe to overwrite R0 with H1
    #pragma unroll
    for (int mt = 0; mt < 2; mt++) {
        int r0 = 32 * wm + 16 * mt + gid;
        #pragma unroll
        for (int nt = 0; nt < 8; nt++) {
            int col = 64 * wn + 8 * nt + 2 * tig;
            float bb0 = b1[col], bb1 = b1[col + 1];
            H1[r0 * H1P + col]     = f2tf(gelu_exact(acc1[mt][nt][0] + bb0));
            H1[r0 * H1P + col + 1] = f2tf(gelu_exact(acc1[mt][nt][1] + bb1));
            H1[(r0 + 8) * H1P + col]     = f2tf(gelu_exact(acc1[mt][nt][2] + bb0));
            H1[(r0 + 8) * H1P + col + 1] = f2tf(gelu_exact(acc1[mt][nt][3] + bb1));
        }
    }

    // ================= Layer 2: 256 -> 128, gelu =================
    float acc2[2][4][4];
    #pragma unroll
    for (int mt = 0; mt < 2; mt++)
        #pragma unroll
        for (int nt = 0; nt < 4; nt++)
            #pragma unroll
            for (int e = 0; e < 4; e++) acc2[mt][nt][e] = 0.f;

    for (int kc = 0; kc < 2; kc++) {
        __syncthreads();
        for (int i = tid; i < 128 * 128; i += 256) {
            int r = i >> 7, c = i & 127;
            Wb[r * W2P + c] = f2tf(W2[(size_t)(kc * 128 + r) * 128 + c]);
        }
        __syncthreads();
        #pragma unroll
        for (int ks = 0; ks < 128; ks += 8) {
            int kg = kc * 128 + ks;
            uint32_t A[2][4];
            #pragma unroll
            for (int mt = 0; mt < 2; mt++) {
                int row = 32 * wm + 16 * mt + gid;
                A[mt][0] = fu(H1[row * H1P + kg + tig]);
                A[mt][1] = fu(H1[(row + 8) * H1P + kg + tig]);
                A[mt][2] = fu(H1[row * H1P + kg + tig + 4]);
                A[mt][3] = fu(H1[(row + 8) * H1P + kg + tig + 4]);
            }
            uint32_t B[4][2];
            #pragma unroll
            for (int nt = 0; nt < 4; nt++) {
                int col = 32 * wn + 8 * nt + gid;
                B[nt][0] = fu(Wb[(ks + tig) * W2P + col]);
                B[nt][1] = fu(Wb[(ks + tig + 4) * W2P + col]);
            }
            #pragma unroll
            for (int mt = 0; mt < 2; mt++)
                #pragma unroll
                for (int nt = 0; nt < 4; nt++) mma_tf32(acc2[mt][nt], A[mt], B[nt]);
        }
    }
    // H2 region (R2) untouched so far; no race with H1 reads (different region)
    #pragma unroll
    for (int mt = 0; mt < 2; mt++) {
        int r0 = 32 * wm + 16 * mt + gid;
        #pragma unroll
        for (int nt = 0; nt < 4; nt++) {
            int col = 32 * wn + 8 * nt + 2 * tig;
            float bb0 = b2[col], bb1 = b2[col + 1];
            H2[r0 * H2P + col]     = f2tf(gelu_exact(acc2[mt][nt][0] + bb0));
            H2[r0 * H2P + col + 1] = f2tf(gelu_exact(acc2[mt][nt][1] + bb1));
            H2[(r0 + 8) * H2P + col]     = f2tf(gelu_exact(acc2[mt][nt][2] + bb0));
            H2[(r0 + 8) * H2P + col + 1] = f2tf(gelu_exact(acc2[mt][nt][3] + bb1));
        }
    }
    __syncthreads();
    // stage W3 (128 x 130 -> padded 136)
    for (int i = tid; i < 128 * 136; i += 256) {
        int r = i / 136, c = i - r * 136;
        Wb[r * W3P + c] = (c < 130) ? f2tf(W3[(size_t)r * 130 + c]) : 0.f;
    }
    __syncthreads();

    // ================= Layer 3: 128 -> 130, linear =================
    size_t dq_off = (size_t)N * 128;
    size_t f_off = dq_off + (size_t)N;
    for (int t = warp; t < 68; t += 8) {      // 4 m-tiles x 17 n-tiles
        int mt = t & 3, nt = t >> 2;
        int m0 = 16 * mt, n0 = 8 * nt;
        float d[4] = {0.f, 0.f, 0.f, 0.f};
        #pragma unroll
        for (int ks = 0; ks < 128; ks += 8) {
            uint32_t A[4], B[2];
            A[0] = fu(H2[(m0 + gid) * H2P + ks + tig]);
            A[1] = fu(H2[(m0 + 8 + gid) * H2P + ks + tig]);
            A[2] = fu(H2[(m0 + gid) * H2P + ks + tig + 4]);
            A[3] = fu(H2[(m0 + 8 + gid) * H2P + ks + tig + 4]);
            B[0] = fu(Wb[(ks + tig) * W3P + n0 + gid]);
            B[1] = fu(Wb[(ks + tig + 4) * W3P + n0 + gid]);
            mma_tf32(d, A, B);
        }
        #pragma unroll
        for (int e = 0; e < 4; e++) {
            int r = m0 + gid + ((e >> 1) ? 8 : 0);
            int j = n0 + 2 * tig + (e & 1);
            int n = a0 + r;
            if (n >= N || j >= 130) continue;
            float v = d[e] + b3[j];
            if (j == 0)      out[dq_off + n] = v;
            else if (j == 1) out[f_off + n] = v;
            else             out[(size_t)n * 128 + (j - 2)] = v;
        }
    }
}

// ---------------------------------------------------------------------------
extern "C" void kernel_launch(void* const* d_in, const int* in_sizes, int n_in,
                              void* d_out, int out_size) {
    const float* emb  = (const float*)d_in[0];
    const float* q    = (const float*)d_in[1];
    const int*   pidx = (const int*)d_in[2];
    const float* gs   = (const float*)d_in[3];
    const float* gv   = (const float*)d_in[4];
    const float* agh  = (const float*)d_in[5];
    const float* Wgf  = (const float*)d_in[6];
    const float* W1   = (const float*)d_in[7];
    const float* b1   = (const float*)d_in[8];
    const float* W2   = (const float*)d_in[9];
    const float* b2   = (const float*)d_in[10];
    const float* W3   = (const float*)d_in[11];
    const float* b3   = (const float*)d_in[12];
    float* out = (float*)d_out;

    int N = in_sizes[0] / 128;
    int P = in_sizes[2] / 2;
    if (N > NMAX) N = NMAX;
    const int* idxj = pidx + P;

    k_zero_acc<<<(N * 16 + 255) / 256, 256>>>(N);

    long long Q = (long long)P * 16;
    k_scatter<<<(int)((Q + 255) / 256), 256>>>(idxj, gs, gv, P);

    int gemm_smem = (64 * XS3 + 128 * WS3) * 4;   // 168960
    cudaFuncSetAttribute(k_gemm_M_tc, cudaFuncAttributeMaxDynamicSharedMemorySize, gemm_smem);
    dim3 g3((N + 63) / 64, 2);
    k_gemm_M_tc<<<g3, 256, gemm_smem>>>(emb, agh, N);

    k_assemble<<<N, 128>>>(emb, q, Wgf, N);

    cudaFuncSetAttribute(k_mlp_tc, cudaFuncAttributeMaxDynamicSharedMemorySize, MLP_SMEM);
    k_mlp_tc<<<(N + 63) / 64, 256, MLP_SMEM>>>(W1, b1, W2, b2, W3, b3, out, N);
}